// round 7
// baseline (speedup 1.0000x reference)
#include <cuda_runtime.h>
#include <cstdint>

#define N_IMG 48
#define H1 512
#define H2 256
#define H3 128
#define NC 20

// Stage-2 output scratch, PLANAR: [n][ic][y][x]  (~63 MB)
__device__ float g_o2[(size_t)N_IMG * NC * H3 * H3];

__device__ __forceinline__ int reflect_idx(int i, int S) {
    if (i < 0) return -i;
    if (i >= S) return 2 * S - 2 - i;
    return i;
}

// ---- packed f32x2 helpers (Blackwell) -------------------------------------
__device__ __forceinline__ uint64_t bcast2(float v) {
    uint64_t r; asm("mov.b64 %0, {%1, %1};" : "=l"(r) : "f"(v)); return r;
}
__device__ __forceinline__ uint64_t pack2(float lo, float hi) {
    uint64_t r; asm("mov.b64 %0, {%1, %2};" : "=l"(r) : "f"(lo), "f"(hi)); return r;
}
__device__ __forceinline__ void ffma2(uint64_t& d, uint64_t a, uint64_t b) {
    asm("fma.rn.f32x2 %0, %1, %2, %0;" : "+l"(d) : "l"(a), "l"(b));
}
__device__ __forceinline__ float2 unpk(uint64_t v) {
    float2 f; asm("mov.b64 {%0, %1}, %2;" : "=f"(f.x), "=f"(f.y) : "l"(v)); return f;
}

// 20 output channels (10 packed oc-pairs) for two pixels sharing one weight fetch.
__device__ __forceinline__ void step20x2(const ulonglong2* __restrict__ w5,
                                         uint64_t v0, uint64_t v1,
                                         uint64_t* a0, uint64_t* a1) {
#pragma unroll
    for (int j = 0; j < 5; j++) {
        ulonglong2 w = w5[j];
        ffma2(a0[2*j],   v0, w.x);
        ffma2(a0[2*j+1], v0, w.y);
        ffma2(a1[2*j],   v1, w.x);
        ffma2(a1[2*j+1], v1, w.y);
    }
}

// ---------------------------------------------------------------------------
// Fused stage1+stage2: x -> (conv1+relu in smem) -> conv2+relu -> planar o2
// Output tile 32x16 of o2 per CTA, 256 threads (16x16), 2 px/thread.
// 4 passes of 5 o1-channels. Target 2 CTAs/SM (109.9 KB smem each).
// ---------------------------------------------------------------------------
#define FT_X_STRIDE 136
#define FT_X_ROWS 70
#define FT_X_COLS 134
#define FT_X_FL (FT_X_ROWS * FT_X_STRIDE)     // 9520
#define FT_O1_STRIDE 68
#define FT_O1_ROWS 34
#define FT_O1_COLS 66
#define FT_O1_PLANE (FT_O1_ROWS * FT_O1_STRIDE)  // 2312
#define FT_O1_FL (5 * FT_O1_PLANE)               // 11560
#define FT_W2_FL (NC * 16 * NC)                  // 6400
#define FT_SMEM ((FT_X_FL + FT_O1_FL + FT_W2_FL) * 4)  // 109920 B

__global__ __launch_bounds__(256, 2) void fused12_kernel(
    const float* __restrict__ x, const float* __restrict__ w1,
    const float* __restrict__ w2)
{
    extern __shared__ __align__(16) float dsm[];
    float* s_x  = dsm;                        // [70][136]
    float* s_o1 = dsm + FT_X_FL;              // [5][34][68]
    float* s_w2 = dsm + FT_X_FL + FT_O1_FL;   // [ic][k][oc]
    __shared__ __align__(16) uint64_t s_w1A[4][16];  // (oc 5p+0, 5p+1)
    __shared__ __align__(16) uint64_t s_w1B[4][16];  // (oc 5p+2, 5p+3)
    __shared__ float s_w1C[4][16];                   //  oc 5p+4

    const int n  = blockIdx.z;
    const int tx = threadIdx.x, ty = threadIdx.y;    // 16 x 16
    const int tid = ty * 16 + tx;
    const int ox0 = blockIdx.x * 32, oy0 = blockIdx.y * 16;
    const int rbase = 2 * oy0 - 1, cbase = 2 * ox0 - 1;   // o1-space origin
    const int xr0 = 4 * oy0 - 3,  xc0 = 4 * ox0 - 3;      // x-space origin

    // w2[oc][ic][k] -> s_w2[ic*320 + k*20 + oc]
    for (int idx = tid; idx < FT_W2_FL; idx += 256) {
        int oc = idx / 320, rem = idx % 320;
        int ic = rem / 16, k = rem % 16;
        s_w2[ic * 320 + k * NC + oc] = w2[idx];
    }
    // w1[oc][k] -> packed per-pass taps (64 elements < 256 threads)
    if (tid < 64) {
        int p = tid / 16, k = tid % 16;
        s_w1A[p][k] = pack2(w1[(5*p + 0) * 16 + k], w1[(5*p + 1) * 16 + k]);
        s_w1B[p][k] = pack2(w1[(5*p + 2) * 16 + k], w1[(5*p + 3) * 16 + k]);
        s_w1C[p][k] = w1[(5*p + 4) * 16 + k];
    }
    // x tile with x-space reflect
    const float* __restrict__ xin = x + (size_t)n * H1 * H1;
    for (int i = tid; i < FT_X_ROWS * FT_X_COLS; i += 256) {
        int r = i / FT_X_COLS, c = i % FT_X_COLS;
        int gr = reflect_idx(xr0 + r, H1);
        int gc = reflect_idx(xc0 + c, H1);
        s_x[r * FT_X_STRIDE + c] = xin[(size_t)gr * H1 + gc];
    }
    __syncthreads();

    uint64_t acc0[10], acc1[10];
#pragma unroll
    for (int j = 0; j < 10; j++) { acc0[j] = 0ull; acc1[j] = 0ull; }

#pragma unroll 1
    for (int p = 0; p < 4; p++) {
        if (p) __syncthreads();   // previous consume done before overwrite

        // ---- produce: o1 channels [5p, 5p+5) over 34x66 slots -------------
        for (int i = tid; i < FT_O1_ROWS * FT_O1_COLS; i += 256) {
            int r = i / FT_O1_COLS, c = i % FT_O1_COLS;
            int pr = 2 * (reflect_idx(rbase + r, H2) - rbase);
            int pc = 2 * (reflect_idx(cbase + c, H2) - cbase);
            uint64_t a01 = 0ull, a23 = 0ull; float a4 = 0.f;
#pragma unroll
            for (int ky = 0; ky < 4; ky++) {
                const float* xr = s_x + (pr + ky) * FT_X_STRIDE + pc;
                float2 A = *(const float2*)xr;
                float2 B = *(const float2*)(xr + 2);
                float v[4] = {A.x, A.y, B.x, B.y};
#pragma unroll
                for (int kx = 0; kx < 4; kx++) {
                    int k = ky * 4 + kx;
                    uint64_t vb = bcast2(v[kx]);
                    ffma2(a01, vb, s_w1A[p][k]);
                    ffma2(a23, vb, s_w1B[p][k]);
                    a4 = fmaf(v[kx], s_w1C[p][k], a4);
                }
            }
            float2 f01 = unpk(a01), f23 = unpk(a23);
            float* dst = s_o1 + r * FT_O1_STRIDE + c;
            dst[0 * FT_O1_PLANE] = fmaxf(f01.x, 0.f);
            dst[1 * FT_O1_PLANE] = fmaxf(f01.y, 0.f);
            dst[2 * FT_O1_PLANE] = fmaxf(f23.x, 0.f);
            dst[3 * FT_O1_PLANE] = fmaxf(f23.y, 0.f);
            dst[4 * FT_O1_PLANE] = fmaxf(a4, 0.f);
        }
        __syncthreads();

        // ---- consume: stage2 over ic = 5p+icl -----------------------------
#pragma unroll 1
        for (int icl = 0; icl < 5; icl++) {
            const float* vbase = s_o1 + icl * FT_O1_PLANE;
            const ulonglong2* wic =
                (const ulonglong2*)(s_w2 + (5*p + icl) * 320);
#pragma unroll
            for (int ky = 0; ky < 4; ky++) {
                const float* vr = vbase + (2 * ty + ky) * FT_O1_STRIDE + 2 * tx;
                float2 a0v = *(const float2*)(vr);
                float2 b0v = *(const float2*)(vr + 2);
                float2 a1v = *(const float2*)(vr + 32);
                float2 b1v = *(const float2*)(vr + 34);
                const ulonglong2* wk = wic + ky * 20;
                step20x2(wk,      bcast2(a0v.x), bcast2(a1v.x), acc0, acc1);
                step20x2(wk + 5,  bcast2(a0v.y), bcast2(a1v.y), acc0, acc1);
                step20x2(wk + 10, bcast2(b0v.x), bcast2(b1v.x), acc0, acc1);
                step20x2(wk + 15, bcast2(b0v.y), bcast2(b1v.y), acc0, acc1);
            }
        }
    }

    // ---- store planar o2: [n][oc][y][x], coalesced scalar stores ----------
    {
        const int py = oy0 + ty;
        float* ob = g_o2 + (((size_t)n * NC) * H3 + py) * H3 + ox0 + tx;
        // plane stride between oc = H3*H3
#pragma unroll
        for (int m = 0; m < 10; m++) {
            float2 p0 = unpk(acc0[m]);   // oc 2m, 2m+1 @ col ox0+tx
            float2 p1 = unpk(acc1[m]);   // oc 2m, 2m+1 @ col ox0+tx+16
            float* o_lo = ob + (size_t)(2*m) * H3 * H3;
            float* o_hi = ob + (size_t)(2*m + 1) * H3 * H3;
            o_lo[0]  = fmaxf(p0.x, 0.f);
            o_lo[16] = fmaxf(p1.x, 0.f);
            o_hi[0]  = fmaxf(p0.y, 0.f);
            o_hi[16] = fmaxf(p1.y, 0.f);
        }
    }
}

// ---------------------------------------------------------------------------
// Stage 3: 3x3 conv zero-pad-1 (20 -> 1) + ReLU, planar input
// tile 32x16 outputs, 256 threads (16x16), 2 adjacent px/thread (f32x2)
// smem: planar [ic][18][36] (plane stride 650), fully unrolled ic x ky
// ---------------------------------------------------------------------------
#define S3_PLANE 650                       // 18*36 + 2 pad
#define S3_SMEM (NC * S3_PLANE * 4)        // 52000 B

__global__ __launch_bounds__(256) void stage3_kernel(
    const float* __restrict__ w3, float* __restrict__ out)
{
    extern __shared__ __align__(16) float s_in[];         // [20][650]
    __shared__ __align__(16) uint64_t s_wd[NC * 9];       // (w,w) pairs

    const int n  = blockIdx.z;
    const int tx = threadIdx.x, ty = threadIdx.y;   // 16 x 16
    const int tid = ty * 16 + tx;
    const int ox0 = blockIdx.x * 32, oy0 = blockIdx.y * 16;

    // 180 elements, 256 threads -> guarded single write is safe here
    if (tid < NC * 9) s_wd[tid] = bcast2(w3[tid]);

    // planar fill: o2[n][ic][gy][gc]
    const float* __restrict__ ip = g_o2 + (size_t)n * NC * H3 * H3;
    for (int idx = tid; idx < NC * 648; idx += 256) {
        int ic = idx / 648, rem = idx % 648;
        int r = rem / 36, c = rem % 36;
        int gy = oy0 - 1 + r, gc = ox0 - 1 + c;
        float v = 0.f;
        if (gy >= 0 && gy < H3 && gc >= 0 && gc < H3)
            v = ip[((size_t)ic * H3 + gy) * H3 + gc];
        s_in[ic * S3_PLANE + r * 36 + c] = v;
    }
    __syncthreads();

    uint64_t acc = 0ull;   // pair = outputs (ox0+2tx, ox0+2tx+1)
#pragma unroll
    for (int ic = 0; ic < NC; ic++) {
#pragma unroll
        for (int ky = 0; ky < 3; ky++) {
            const float* vr = s_in + ic * S3_PLANE + (ty + ky) * 36 + 2 * tx;
            uint64_t vA = *(const uint64_t*)(vr);
            uint64_t vB = *(const uint64_t*)(vr + 2);
            uint64_t vM = (vA >> 32) | (vB << 32);
            ffma2(acc, vA, s_wd[ic * 9 + ky * 3 + 0]);
            ffma2(acc, vM, s_wd[ic * 9 + ky * 3 + 1]);
            ffma2(acc, vB, s_wd[ic * 9 + ky * 3 + 2]);
        }
    }

    float2 f = unpk(acc);
    float2 o = make_float2(fmaxf(f.x, 0.f), fmaxf(f.y, 0.f));
    *(float2*)(out + ((size_t)n * H3 + (oy0 + ty)) * H3 + ox0 + 2 * tx) = o;
}

// ---------------------------------------------------------------------------
extern "C" void kernel_launch(void* const* d_in, const int* in_sizes, int n_in,
                              void* d_out, int out_size)
{
    const float* x  = (const float*)d_in[0];
    const float* w1 = (const float*)d_in[1];
    const float* w2 = (const float*)d_in[2];
    const float* w3 = (const float*)d_in[3];
    float* out = (float*)d_out;

    cudaFuncSetAttribute(fused12_kernel,
                         cudaFuncAttributeMaxDynamicSharedMemorySize, FT_SMEM);
    cudaFuncSetAttribute(stage3_kernel,
                         cudaFuncAttributeMaxDynamicSharedMemorySize, S3_SMEM);

    fused12_kernel<<<dim3(4, 8, N_IMG), dim3(16, 16), FT_SMEM>>>(x, w1, w2);
    stage3_kernel<<<dim3(4, 8, N_IMG), dim3(16, 16), S3_SMEM>>>(w3, out);
}

// round 9
// speedup vs baseline: 1.0635x; 1.0635x over previous
#include <cuda_runtime.h>
#include <cuda_bf16.h>
#include <cstdint>

#define N_IMG 48
#define H1 512
#define H2 256
#define H3 128
#define NC 20

// o2 scratch, channels-last [n][y][x][ic] (~63 MB)
__device__ float g_o2[(size_t)N_IMG * H3 * H3 * NC];
// Precomputed stage-2 weights, bf16 hi/lo, u32-packed pairs: [24 oc][164]
__device__ uint32_t g_Bh[24 * 164];
__device__ uint32_t g_Bl[24 * 164];

__device__ __forceinline__ int reflect_idx(int i, int S) {
    if (i < 0) return -i;
    if (i >= S) return 2 * S - 2 - i;
    return i;
}

// ---- packed f32x2 helpers --------------------------------------------------
__device__ __forceinline__ uint64_t bcast2(float v) {
    uint64_t r; asm("mov.b64 %0, {%1, %1};" : "=l"(r) : "f"(v)); return r;
}
__device__ __forceinline__ uint64_t pack2(float lo, float hi) {
    uint64_t r; asm("mov.b64 %0, {%1, %2};" : "=l"(r) : "f"(lo), "f"(hi)); return r;
}
__device__ __forceinline__ void ffma2(uint64_t& d, uint64_t a, uint64_t b) {
    asm("fma.rn.f32x2 %0, %1, %2, %0;" : "+l"(d) : "l"(a), "l"(b));
}
__device__ __forceinline__ float2 unpk(uint64_t v) {
    float2 f; asm("mov.b64 {%0, %1}, %2;" : "=f"(f.x), "=f"(f.y) : "l"(v)); return f;
}

__device__ __forceinline__ uint16_t bf16_bits(float v) {
    __nv_bfloat16 h = __float2bfloat16_rn(v);
    return *(uint16_t*)&h;
}
__device__ __forceinline__ float bf16_back(uint16_t b) {
    uint32_t u = ((uint32_t)b) << 16;
    return __uint_as_float(u);
}

// mma.sync m16n8k16 row.col f32 = bf16 x bf16 + f32
__device__ __forceinline__ void mma16816(float* c, const uint32_t* a,
                                         uint32_t b0, uint32_t b1) {
    asm volatile(
        "mma.sync.aligned.m16n8k16.row.col.f32.bf16.bf16.f32 "
        "{%0,%1,%2,%3}, {%4,%5,%6,%7}, {%8,%9}, {%0,%1,%2,%3};"
        : "+f"(c[0]), "+f"(c[1]), "+f"(c[2]), "+f"(c[3])
        : "r"(a[0]), "r"(a[1]), "r"(a[2]), "r"(a[3]), "r"(b0), "r"(b1));
}

// ---------------------------------------------------------------------------
// Prep: w2 -> bf16 hi/lo packed u32 [24 oc][164] (rows 20..23, cols 160.. = 0)
// ---------------------------------------------------------------------------
__global__ void prep_kernel(const float* __restrict__ w2)
{
    int idx = blockIdx.x * 256 + threadIdx.x;
    if (idx >= 24 * 164) return;
    int n = idx / 164, j = idx % 164;
    uint32_t hv = 0, lv = 0;
    if (n < NC && j < 160) {
        float v0 = w2[n * 320 + 2 * j];
        float v1 = w2[n * 320 + 2 * j + 1];
        uint16_t h0 = bf16_bits(v0), h1 = bf16_bits(v1);
        uint16_t l0 = bf16_bits(v0 - bf16_back(h0));
        uint16_t l1 = bf16_bits(v1 - bf16_back(h1));
        hv = ((uint32_t)h1 << 16) | h0;
        lv = ((uint32_t)l1 << 16) | l0;
    }
    g_Bh[idx] = hv;
    g_Bl[idx] = lv;
}

// ---------------------------------------------------------------------------
// Fused stage1+stage2: x -> o1(bf16 hi/lo in smem) -> mma.sync -> o2
// CTA: 128 threads (4 warps), 16x8 o2 output px.
// smem: s_x[38][72] f32 | o1h[20][18][40] u16 | o1l same | Bh[24][164] u32 | Bl
// ---------------------------------------------------------------------------
#define SX_STRIDE 72
#define OFF_SX 0
#define SX_BYTES (38 * SX_STRIDE * 4)            // 10944
#define OFF_O1H SX_BYTES                          // 10944
#define O1_PLANE_BYTES (18 * 40 * 2)              // 1440 (u16 rows stride 40)
#define O1_BYTES (NC * O1_PLANE_BYTES)            // 28800
#define OFF_O1L (OFF_O1H + O1_BYTES)              // 39744
#define OFF_BH (OFF_O1L + O1_BYTES)               // 68544
#define B_BYTES (24 * 164 * 4)                    // 15744
#define OFF_BL (OFF_BH + B_BYTES)                 // 84288
#define FK_SMEM (OFF_BL + B_BYTES)                // 100032

__global__ __launch_bounds__(128) void fused_mma_kernel(
    const float* __restrict__ x, const float* __restrict__ w1)
{
    extern __shared__ __align__(16) char dsm[];
    float* s_x = (float*)(dsm + OFF_SX);
    uint16_t* o1h16 = (uint16_t*)(dsm + OFF_O1H);
    uint16_t* o1l16 = (uint16_t*)(dsm + OFF_O1L);
    uint32_t* sBh = (uint32_t*)(dsm + OFF_BH);
    uint32_t* sBl = (uint32_t*)(dsm + OFF_BL);
    __shared__ __align__(16) uint64_t w1p[16][10];   // [tap][oc-pair]

    const int n  = blockIdx.z;
    const int tid = threadIdx.x;
    const int ox0 = blockIdx.x * 16, oy0 = blockIdx.y * 8;
    const int rbase = 2 * oy0 - 1, cbase = 2 * ox0 - 1;   // o1-space origin
    const int xr0 = 4 * oy0 - 3,  xc0 = 4 * ox0 - 3;      // x-space origin

    // ---- B copy to smem ----------------------------------------------------
    for (int i = tid; i < 24 * 164; i += 128) {
        sBh[i] = g_Bh[i];
        sBl[i] = g_Bl[i];
    }
    // ---- w1 packed taps (160 entries, strided) -----------------------------
    for (int idx = tid; idx < 160; idx += 128) {
        int k = idx / 10, j = idx % 10;
        w1p[k][j] = pack2(w1[(2*j) * 16 + k], w1[(2*j + 1) * 16 + k]);
    }
    // ---- x tile (38 x 70, reflect) -----------------------------------------
    const float* __restrict__ xin = x + (size_t)n * H1 * H1;
    for (int i = tid; i < 38 * 70; i += 128) {
        int r = i / 70, c = i % 70;
        int gr = reflect_idx(xr0 + r, H1);
        int gc = reflect_idx(xc0 + c, H1);
        s_x[r * SX_STRIDE + c] = xin[(size_t)gr * H1 + gc];
    }
    __syncthreads();

    // ---- produce o1 (18 x 34 slots, 20 ch) as bf16 hi/lo -------------------
    for (int i = tid; i < 18 * 34; i += 128) {
        int r = i / 34, c = i % 34;
        int pr = 2 * (reflect_idx(rbase + r, H2) - rbase);
        int pc = 2 * (reflect_idx(cbase + c, H2) - cbase);
        uint64_t acc[10];
#pragma unroll
        for (int j = 0; j < 10; j++) acc[j] = 0ull;
#pragma unroll
        for (int ky = 0; ky < 4; ky++) {
            const float* xr = s_x + (pr + ky) * SX_STRIDE + pc;
            float2 A = *(const float2*)xr;
            float2 B = *(const float2*)(xr + 2);
            float v[4] = {A.x, A.y, B.x, B.y};
#pragma unroll
            for (int kx = 0; kx < 4; kx++) {
                uint64_t vb = bcast2(v[kx]);
                const uint64_t* wk = w1p[ky * 4 + kx];
#pragma unroll
                for (int j = 0; j < 10; j++) ffma2(acc[j], vb, wk[j]);
            }
        }
        int base16 = r * 40 + c;   // within a plane (u16 units)
#pragma unroll
        for (int j = 0; j < 10; j++) {
            float2 f = unpk(acc[j]);
            float v0 = fmaxf(f.x, 0.f), v1 = fmaxf(f.y, 0.f);
            uint16_t h0 = bf16_bits(v0), h1 = bf16_bits(v1);
            uint16_t l0 = bf16_bits(v0 - bf16_back(h0));
            uint16_t l1 = bf16_bits(v1 - bf16_back(h1));
            o1h16[(2*j)     * 720 + base16] = h0;
            o1h16[(2*j + 1) * 720 + base16] = h1;
            o1l16[(2*j)     * 720 + base16] = l0;
            o1l16[(2*j + 1) * 720 + base16] = l1;
        }
    }
    __syncthreads();

    // ---- consume: mma.sync, 8 m-tiles (py rows) x 3 n-tiles x 20 k-steps ---
    const int l = tid & 31, w = tid >> 5;
    const int g = l >> 2, q = l & 3;          // groupID, tid-in-group
    const uint32_t* o1h = (const uint32_t*)o1h16;   // [ic][18][20] u32
    const uint32_t* o1l = (const uint32_t*)o1l16;
    const int ky0 = q >> 1;                   // k-lo: ky
    const int kxh = q & 1;                    // k-lo: kx/2

    float acc[2][3][4];
#pragma unroll
    for (int t = 0; t < 2; t++)
#pragma unroll
        for (int nt = 0; nt < 3; nt++)
#pragma unroll
            for (int e = 0; e < 4; e++) acc[t][nt][e] = 0.f;

#pragma unroll 1
    for (int ic = 0; ic < NC; ic++) {
        const int pb = ic * 360;
        uint32_t ah[2][4], al[2][4];
#pragma unroll
        for (int t = 0; t < 2; t++) {
            int py = 2 * w + t;
            int row_lo = pb + (2 * py + ky0) * 20;
            int row_hi = pb + (2 * py + ky0 + 2) * 20;
            ah[t][0] = o1h[row_lo + g + kxh];
            ah[t][1] = o1h[row_lo + g + 8 + kxh];
            ah[t][2] = o1h[row_hi + g + kxh];
            ah[t][3] = o1h[row_hi + g + 8 + kxh];
            al[t][0] = o1l[row_lo + g + kxh];
            al[t][1] = o1l[row_lo + g + 8 + kxh];
            al[t][2] = o1l[row_hi + g + kxh];
            al[t][3] = o1l[row_hi + g + 8 + kxh];
        }
#pragma unroll
        for (int nt = 0; nt < 3; nt++) {
            int bi = (nt * 8 + g) * 164 + ic * 8 + q;
            uint32_t bh0 = sBh[bi], bh1 = sBh[bi + 4];
            uint32_t bl0 = sBl[bi], bl1 = sBl[bi + 4];
#pragma unroll
            for (int t = 0; t < 2; t++) {
                mma16816(acc[t][nt], ah[t], bh0, bh1);   // hi*hi
                mma16816(acc[t][nt], ah[t], bl0, bl1);   // hi*lo
                mma16816(acc[t][nt], al[t], bh0, bh1);   // lo*hi
            }
        }
    }

    // ---- drain accumulators, relu, store channels-last ---------------------
#pragma unroll
    for (int t = 0; t < 2; t++) {
        int y = oy0 + 2 * w + t;
#pragma unroll
        for (int nt = 0; nt < 3; nt++) {
            int oc = nt * 8 + 2 * q;
            if (oc < NC) {
                float* p0 = g_o2 + (((size_t)n * H3 + y) * H3 + ox0 + g) * NC + oc;
                float* p1 = g_o2 + (((size_t)n * H3 + y) * H3 + ox0 + g + 8) * NC + oc;
                float2 v0 = make_float2(fmaxf(acc[t][nt][0], 0.f),
                                        fmaxf(acc[t][nt][1], 0.f));
                float2 v1 = make_float2(fmaxf(acc[t][nt][2], 0.f),
                                        fmaxf(acc[t][nt][3], 0.f));
                *(float2*)p0 = v0;
                *(float2*)p1 = v1;
            }
        }
    }
}

// ---------------------------------------------------------------------------
// Stage 3: 3x3 conv zero-pad-1 (20 -> 1) + ReLU  (R6 version, measured 44us)
// ---------------------------------------------------------------------------
#define S3_ICSTR 362

__global__ __launch_bounds__(128) void stage3_kernel(
    const float* __restrict__ w3, float* __restrict__ out)
{
    __shared__ __align__(16) float s_in[NC * S3_ICSTR];
    __shared__ __align__(16) uint64_t s_wd[NC * 9];

    const int n  = blockIdx.z;
    const int tx = threadIdx.x, ty = threadIdx.y;   // 16 x 8
    const int tid = ty * 16 + tx;
    const int ox0 = blockIdx.x * 32, oy0 = blockIdx.y * 8;

    for (int idx = tid; idx < NC * 9; idx += 128)
        s_wd[idx] = bcast2(w3[idx]);

    const float* __restrict__ ip = g_o2 + (size_t)n * H3 * H3 * NC;
    for (int idx = tid; idx < 360 * NC; idx += 128) {
        int pix = idx / NC, ic = idx % NC;
        int r = pix / 36, c = pix % 36;
        int gy = oy0 - 1 + r, gc = ox0 - 1 + c;
        float v = 0.f;
        if (gy >= 0 && gy < H3 && gc >= 0 && gc < H3)
            v = ip[((size_t)gy * H3 + gc) * NC + ic];
        s_in[ic * S3_ICSTR + pix] = v;
    }
    __syncthreads();

    uint64_t acc = 0ull;
#pragma unroll 4
    for (int ic = 0; ic < NC; ic++) {
        const float* base = s_in + ic * S3_ICSTR;
        const uint64_t* wic = s_wd + ic * 9;
#pragma unroll
        for (int ky = 0; ky < 3; ky++) {
            const float* vr = base + (ty + ky) * 36 + 2 * tx;
            uint64_t vA = *(const uint64_t*)(vr);
            uint64_t vB = *(const uint64_t*)(vr + 2);
            uint64_t vM = (vA >> 32) | (vB << 32);
            ffma2(acc, vA, wic[ky * 3 + 0]);
            ffma2(acc, vM, wic[ky * 3 + 1]);
            ffma2(acc, vB, wic[ky * 3 + 2]);
        }
    }

    float2 f = unpk(acc);
    float2 o = make_float2(fmaxf(f.x, 0.f), fmaxf(f.y, 0.f));
    *(float2*)(out + ((size_t)n * H3 + (oy0 + ty)) * H3 + ox0 + 2 * tx) = o;
}

// ---------------------------------------------------------------------------
extern "C" void kernel_launch(void* const* d_in, const int* in_sizes, int n_in,
                              void* d_out, int out_size)
{
    const float* x  = (const float*)d_in[0];
    const float* w1 = (const float*)d_in[1];
    const float* w2 = (const float*)d_in[2];
    const float* w3 = (const float*)d_in[3];
    float* out = (float*)d_out;

    cudaFuncSetAttribute(fused_mma_kernel,
                         cudaFuncAttributeMaxDynamicSharedMemorySize, FK_SMEM);

    prep_kernel<<<16, 256>>>(w2);
    fused_mma_kernel<<<dim3(8, 16, N_IMG), dim3(128), FK_SMEM>>>(x, w1);
    stage3_kernel<<<dim3(4, 16, N_IMG), dim3(16, 8)>>>(w3, out);
}

// round 10
// speedup vs baseline: 1.0695x; 1.0056x over previous
#include <cuda_runtime.h>
#include <cuda_bf16.h>
#include <cstdint>

#define N_IMG 48
#define H1 512
#define H2 256
#define H3 128
#define NC 20

// o2 scratch, channels-last [n][y][x][ic] (~63 MB)
__device__ float g_o2[(size_t)N_IMG * H3 * H3 * NC];
// Precomputed stage-2 weights, bf16 hi/lo, u32-packed pairs: [24 oc][164]
__device__ uint32_t g_Bh[24 * 164];
__device__ uint32_t g_Bl[24 * 164];

__device__ __forceinline__ int reflect_idx(int i, int S) {
    if (i < 0) return -i;
    if (i >= S) return 2 * S - 2 - i;
    return i;
}

// ---- packed f32x2 helpers --------------------------------------------------
__device__ __forceinline__ uint64_t bcast2(float v) {
    uint64_t r; asm("mov.b64 %0, {%1, %1};" : "=l"(r) : "f"(v)); return r;
}
__device__ __forceinline__ uint64_t pack2(float lo, float hi) {
    uint64_t r; asm("mov.b64 %0, {%1, %2};" : "=l"(r) : "f"(lo), "f"(hi)); return r;
}
__device__ __forceinline__ void ffma2(uint64_t& d, uint64_t a, uint64_t b) {
    asm("fma.rn.f32x2 %0, %1, %2, %0;" : "+l"(d) : "l"(a), "l"(b));
}
__device__ __forceinline__ float2 unpk(uint64_t v) {
    float2 f; asm("mov.b64 {%0, %1}, %2;" : "=f"(f.x), "=f"(f.y) : "l"(v)); return f;
}

__device__ __forceinline__ uint16_t bf16_bits(float v) {
    __nv_bfloat16 h = __float2bfloat16_rn(v);
    return *(uint16_t*)&h;
}
__device__ __forceinline__ float bf16_back(uint16_t b) {
    uint32_t u = ((uint32_t)b) << 16;
    return __uint_as_float(u);
}

// mma.sync m16n8k16 row.col f32 = bf16 x bf16 + f32
__device__ __forceinline__ void mma16816(float* c, const uint32_t* a,
                                         uint32_t b0, uint32_t b1) {
    asm volatile(
        "mma.sync.aligned.m16n8k16.row.col.f32.bf16.bf16.f32 "
        "{%0,%1,%2,%3}, {%4,%5,%6,%7}, {%8,%9}, {%0,%1,%2,%3};"
        : "+f"(c[0]), "+f"(c[1]), "+f"(c[2]), "+f"(c[3])
        : "r"(a[0]), "r"(a[1]), "r"(a[2]), "r"(a[3]), "r"(b0), "r"(b1));
}

// ---------------------------------------------------------------------------
// Prep: w2 -> bf16 hi/lo packed u32 [24 oc][164]
// ---------------------------------------------------------------------------
__global__ void prep_kernel(const float* __restrict__ w2)
{
    int idx = blockIdx.x * 256 + threadIdx.x;
    if (idx >= 24 * 164) return;
    int n = idx / 164, j = idx % 164;
    uint32_t hv = 0, lv = 0;
    if (n < NC && j < 160) {
        float v0 = w2[n * 320 + 2 * j];
        float v1 = w2[n * 320 + 2 * j + 1];
        uint16_t h0 = bf16_bits(v0), h1 = bf16_bits(v1);
        uint16_t l0 = bf16_bits(v0 - bf16_back(h0));
        uint16_t l1 = bf16_bits(v1 - bf16_back(h1));
        hv = ((uint32_t)h1 << 16) | h0;
        lv = ((uint32_t)l1 << 16) | l0;
    }
    g_Bh[idx] = hv;
    g_Bl[idx] = lv;
}

// ---------------------------------------------------------------------------
// Fused stage1+stage2: x -> o1(bf16 hi/lo in smem) -> mma.sync -> o2
// CTA: 128 threads (4 warps), 16x8 o2 output px. Target 3 CTAs/SM.
// smem: s_x[38][72] f32 | o1h[20][18][36] u16 | o1l same   (61.3 KB)
// B fragments read straight from gmem (L1-resident, 12.6 KB shared by all).
// ---------------------------------------------------------------------------
#define SX_STRIDE 72
#define OFF_SX 0
#define SX_BYTES (38 * SX_STRIDE * 4)            // 10944
#define OFF_O1H SX_BYTES                          // 10944
#define O1_PLANE16 648                            // 18*36 u16 per channel
#define O1_BYTES (NC * O1_PLANE16 * 2)            // 25920
#define OFF_O1L (OFF_O1H + O1_BYTES)              // 36864
#define FK_SMEM (OFF_O1L + O1_BYTES)              // 62784

__global__ __launch_bounds__(128, 3) void fused_mma_kernel(
    const float* __restrict__ x, const float* __restrict__ w1)
{
    extern __shared__ __align__(16) char dsm[];
    float* s_x = (float*)(dsm + OFF_SX);
    uint16_t* o1h16 = (uint16_t*)(dsm + OFF_O1H);
    uint16_t* o1l16 = (uint16_t*)(dsm + OFF_O1L);
    __shared__ __align__(16) uint64_t w1p[16][10];   // [tap][oc-pair]

    const int n  = blockIdx.z;
    const int tid = threadIdx.x;
    const int ox0 = blockIdx.x * 16, oy0 = blockIdx.y * 8;
    const int rbase = 2 * oy0 - 1, cbase = 2 * ox0 - 1;   // o1-space origin
    const int xr0 = 4 * oy0 - 3,  xc0 = 4 * ox0 - 3;      // x-space origin

    // ---- w1 packed taps (160 entries, strided) -----------------------------
    for (int idx = tid; idx < 160; idx += 128) {
        int k = idx / 10, j = idx % 10;
        w1p[k][j] = pack2(w1[(2*j) * 16 + k], w1[(2*j + 1) * 16 + k]);
    }
    // ---- x tile (38 x 70, reflect) -----------------------------------------
    const float* __restrict__ xin = x + (size_t)n * H1 * H1;
    for (int i = tid; i < 38 * 70; i += 128) {
        int r = i / 70, c = i % 70;
        int gr = reflect_idx(xr0 + r, H1);
        int gc = reflect_idx(xc0 + c, H1);
        s_x[r * SX_STRIDE + c] = xin[(size_t)gr * H1 + gc];
    }
    __syncthreads();

    // ---- produce o1 (18 x 34 slots, 20 ch) as bf16 hi/lo -------------------
    for (int i = tid; i < 18 * 34; i += 128) {
        int r = i / 34, c = i % 34;
        int pr = 2 * (reflect_idx(rbase + r, H2) - rbase);
        int pc = 2 * (reflect_idx(cbase + c, H2) - cbase);
        uint64_t acc[10];
#pragma unroll
        for (int j = 0; j < 10; j++) acc[j] = 0ull;
#pragma unroll
        for (int ky = 0; ky < 4; ky++) {
            const float* xr = s_x + (pr + ky) * SX_STRIDE + pc;
            float2 A = *(const float2*)xr;
            float2 B = *(const float2*)(xr + 2);
            float v[4] = {A.x, A.y, B.x, B.y};
#pragma unroll
            for (int kx = 0; kx < 4; kx++) {
                uint64_t vb = bcast2(v[kx]);
                const uint64_t* wk = w1p[ky * 4 + kx];
#pragma unroll
                for (int j = 0; j < 10; j++) ffma2(acc[j], vb, wk[j]);
            }
        }
        int base16 = r * 36 + c;   // within a plane (u16 units)
#pragma unroll
        for (int j = 0; j < 10; j++) {
            float2 f = unpk(acc[j]);
            float v0 = fmaxf(f.x, 0.f), v1 = fmaxf(f.y, 0.f);
            uint16_t h0 = bf16_bits(v0), h1 = bf16_bits(v1);
            uint16_t l0 = bf16_bits(v0 - bf16_back(h0));
            uint16_t l1 = bf16_bits(v1 - bf16_back(h1));
            o1h16[(2*j)     * O1_PLANE16 + base16] = h0;
            o1h16[(2*j + 1) * O1_PLANE16 + base16] = h1;
            o1l16[(2*j)     * O1_PLANE16 + base16] = l0;
            o1l16[(2*j + 1) * O1_PLANE16 + base16] = l1;
        }
    }
    __syncthreads();

    // ---- consume: mma.sync, 2 m-tiles/warp x 3 n-tiles x 20 ic x 3 terms ---
    const int l = tid & 31, w = tid >> 5;
    const int g = l >> 2, q = l & 3;          // groupID, tid-in-group
    const uint32_t* o1h = (const uint32_t*)o1h16;   // [ic][18 rows][18 u32]
    const uint32_t* o1l = (const uint32_t*)o1l16;
    const int ky0 = q >> 1;
    const int kxh = q & 1;

    float acc[2][3][4];
#pragma unroll
    for (int t = 0; t < 2; t++)
#pragma unroll
        for (int nt = 0; nt < 3; nt++)
#pragma unroll
            for (int e = 0; e < 4; e++) acc[t][nt][e] = 0.f;

#pragma unroll 2
    for (int ic = 0; ic < NC; ic++) {
        const int pb = ic * 324;              // 18*18 u32 per channel
        uint32_t ah[2][4], al[2][4];
#pragma unroll
        for (int t = 0; t < 2; t++) {
            int py = 2 * w + t;
            int row_lo = pb + (2 * py + ky0) * 18;
            int row_hi = pb + (2 * py + ky0 + 2) * 18;
            ah[t][0] = o1h[row_lo + g + kxh];
            ah[t][1] = o1h[row_lo + g + 8 + kxh];
            ah[t][2] = o1h[row_hi + g + kxh];
            ah[t][3] = o1h[row_hi + g + 8 + kxh];
            al[t][0] = o1l[row_lo + g + kxh];
            al[t][1] = o1l[row_lo + g + 8 + kxh];
            al[t][2] = o1l[row_hi + g + kxh];
            al[t][3] = o1l[row_hi + g + 8 + kxh];
        }
#pragma unroll
        for (int nt = 0; nt < 3; nt++) {
            int bi = (nt * 8 + g) * 164 + ic * 8 + q;
            uint32_t bh0 = __ldg(&g_Bh[bi]), bh1 = __ldg(&g_Bh[bi + 4]);
            uint32_t bl0 = __ldg(&g_Bl[bi]), bl1 = __ldg(&g_Bl[bi + 4]);
#pragma unroll
            for (int t = 0; t < 2; t++) {
                mma16816(acc[t][nt], ah[t], bh0, bh1);   // hi*hi
                mma16816(acc[t][nt], ah[t], bl0, bl1);   // hi*lo
                mma16816(acc[t][nt], al[t], bh0, bh1);   // lo*hi
            }
        }
    }

    // ---- drain accumulators, relu, store channels-last ---------------------
#pragma unroll
    for (int t = 0; t < 2; t++) {
        int y = oy0 + 2 * w + t;
#pragma unroll
        for (int nt = 0; nt < 3; nt++) {
            int oc = nt * 8 + 2 * q;
            if (oc < NC) {
                float* p0 = g_o2 + (((size_t)n * H3 + y) * H3 + ox0 + g) * NC + oc;
                float* p1 = g_o2 + (((size_t)n * H3 + y) * H3 + ox0 + g + 8) * NC + oc;
                float2 v0 = make_float2(fmaxf(acc[t][nt][0], 0.f),
                                        fmaxf(acc[t][nt][1], 0.f));
                float2 v1 = make_float2(fmaxf(acc[t][nt][2], 0.f),
                                        fmaxf(acc[t][nt][3], 0.f));
                *(float2*)p0 = v0;
                *(float2*)p1 = v1;
            }
        }
    }
}

// ---------------------------------------------------------------------------
// Stage 3: 3x3 conv zero-pad-1 (20 -> 1) + ReLU
// tile 32x8 outputs, 128 threads; float4 gather fill, fully unrolled consume
// ---------------------------------------------------------------------------
#define S3_PLANE 362   // 10*36 + 2 pad (floats)

__global__ __launch_bounds__(128) void stage3_kernel(
    const float* __restrict__ w3, float* __restrict__ out)
{
    __shared__ __align__(16) float s_in[NC * S3_PLANE];
    __shared__ __align__(16) uint64_t s_wd[NC * 9];

    const int n  = blockIdx.z;
    const int tx = threadIdx.x, ty = threadIdx.y;   // 16 x 8
    const int tid = ty * 16 + tx;
    const int ox0 = blockIdx.x * 32, oy0 = blockIdx.y * 8;

    for (int idx = tid; idx < NC * 9; idx += 128)
        s_wd[idx] = bcast2(w3[idx]);

    // fill: 10 rows x 34 cols x 20 ch via float4 (5 per pixel)
    const float* __restrict__ ip = g_o2 + (size_t)n * H3 * H3 * NC;
    for (int i = tid; i < 340 * 5; i += 128) {
        int px = i / 5, j = i % 5;
        int r = px / 34, c = px % 34;
        int gy = oy0 - 1 + r, gx = ox0 - 1 + c;
        float4 v = make_float4(0.f, 0.f, 0.f, 0.f);
        if (gy >= 0 && gy < H3 && gx >= 0 && gx < H3)
            v = *(const float4*)(ip + ((size_t)gy * H3 + gx) * NC + 4 * j);
        float* dst = s_in + (4 * j) * S3_PLANE + r * 36 + c;
        dst[0 * S3_PLANE] = v.x;
        dst[1 * S3_PLANE] = v.y;
        dst[2 * S3_PLANE] = v.z;
        dst[3 * S3_PLANE] = v.w;
    }
    __syncthreads();

    uint64_t acc = 0ull;   // pair = outputs (ox0+2tx, ox0+2tx+1)
#pragma unroll
    for (int ic = 0; ic < NC; ic++) {
#pragma unroll
        for (int ky = 0; ky < 3; ky++) {
            const float* vr = s_in + ic * S3_PLANE + (ty + ky) * 36 + 2 * tx;
            uint64_t vA = *(const uint64_t*)(vr);
            uint64_t vB = *(const uint64_t*)(vr + 2);
            uint64_t vM = (vA >> 32) | (vB << 32);
            ffma2(acc, vA, s_wd[ic * 9 + ky * 3 + 0]);
            ffma2(acc, vM, s_wd[ic * 9 + ky * 3 + 1]);
            ffma2(acc, vB, s_wd[ic * 9 + ky * 3 + 2]);
        }
    }

    float2 f = unpk(acc);
    float2 o = make_float2(fmaxf(f.x, 0.f), fmaxf(f.y, 0.f));
    *(float2*)(out + ((size_t)n * H3 + (oy0 + ty)) * H3 + ox0 + 2 * tx) = o;
}

// ---------------------------------------------------------------------------
extern "C" void kernel_launch(void* const* d_in, const int* in_sizes, int n_in,
                              void* d_out, int out_size)
{
    const float* x  = (const float*)d_in[0];
    const float* w1 = (const float*)d_in[1];
    const float* w2 = (const float*)d_in[2];
    const float* w3 = (const float*)d_in[3];
    float* out = (float*)d_out;

    cudaFuncSetAttribute(fused_mma_kernel,
                         cudaFuncAttributeMaxDynamicSharedMemorySize, FK_SMEM);

    prep_kernel<<<16, 256>>>(w2);
    fused_mma_kernel<<<dim3(8, 16, N_IMG), dim3(128), FK_SMEM>>>(x, w1);
    stage3_kernel<<<dim3(4, 16, N_IMG), dim3(16, 8)>>>(w3, out);
}

// round 11
// speedup vs baseline: 1.1549x; 1.0798x over previous
#include <cuda_runtime.h>
#include <cuda_bf16.h>
#include <cstdint>

#define N_IMG 48
#define H1 512
#define H2 256
#define H3 128
#define NC 20

// o2 scratch, channels-last [n][y][x][ic] (~63 MB)
__device__ float g_o2[(size_t)N_IMG * H3 * H3 * NC];
// Stage-2 weight fragments, lane-linear: [ic][nt][lane] -> (bh0,bh1,bl0,bl1)
__device__ uint4 g_B2[NC * 3 * 32];

__device__ __forceinline__ int reflect_idx(int i, int S) {
    if (i < 0) return -i;
    if (i >= S) return 2 * S - 2 - i;
    return i;
}

// ---- packed f32x2 helpers --------------------------------------------------
__device__ __forceinline__ uint64_t bcast2(float v) {
    uint64_t r; asm("mov.b64 %0, {%1, %1};" : "=l"(r) : "f"(v)); return r;
}
__device__ __forceinline__ uint64_t pack2(float lo, float hi) {
    uint64_t r; asm("mov.b64 %0, {%1, %2};" : "=l"(r) : "f"(lo), "f"(hi)); return r;
}
__device__ __forceinline__ void ffma2(uint64_t& d, uint64_t a, uint64_t b) {
    asm("fma.rn.f32x2 %0, %1, %2, %0;" : "+l"(d) : "l"(a), "l"(b));
}
__device__ __forceinline__ float2 unpk(uint64_t v) {
    float2 f; asm("mov.b64 {%0, %1}, %2;" : "=f"(f.x), "=f"(f.y) : "l"(v)); return f;
}

__device__ __forceinline__ uint16_t bf16_bits(float v) {
    __nv_bfloat16 h = __float2bfloat16_rn(v);
    return *(uint16_t*)&h;
}
__device__ __forceinline__ float bf16_back(uint16_t b) {
    uint32_t u = ((uint32_t)b) << 16;
    return __uint_as_float(u);
}

// mma.sync m16n8k16 row.col f32 = bf16 x bf16 + f32
__device__ __forceinline__ void mma16816(float* c, const uint32_t* a,
                                         uint32_t b0, uint32_t b1) {
    asm volatile(
        "mma.sync.aligned.m16n8k16.row.col.f32.bf16.bf16.f32 "
        "{%0,%1,%2,%3}, {%4,%5,%6,%7}, {%8,%9}, {%0,%1,%2,%3};"
        : "+f"(c[0]), "+f"(c[1]), "+f"(c[2]), "+f"(c[3])
        : "r"(a[0]), "r"(a[1]), "r"(a[2]), "r"(a[3]), "r"(b0), "r"(b1));
}

// ---------------------------------------------------------------------------
// Prep: w2 -> lane-linear bf16 hi/lo fragment table g_B2[ic][nt][lane]
// lane l: g = l>>2 (col of B tile), q = l&3 (k-group)
// value: bh0 = cols (ic*16+2q, +1) of oc n=nt*8+g;  bh1 = cols (+8, +9)
// ---------------------------------------------------------------------------
__global__ void prep_kernel(const float* __restrict__ w2)
{
    int idx = blockIdx.x * 256 + threadIdx.x;
    if (idx >= NC * 3 * 32) return;
    int ic = idx / 96, rem = idx % 96;
    int nt = rem / 32, l = rem % 32;
    int g = l >> 2, q = l & 3;
    int n = nt * 8 + g;
    uint4 v = make_uint4(0, 0, 0, 0);
    if (n < NC) {
        int c0 = ic * 16 + 2 * q;
        float a0 = w2[n * 320 + c0],     a1 = w2[n * 320 + c0 + 1];
        float a8 = w2[n * 320 + c0 + 8], a9 = w2[n * 320 + c0 + 9];
        uint16_t h0 = bf16_bits(a0), h1 = bf16_bits(a1);
        uint16_t h8 = bf16_bits(a8), h9 = bf16_bits(a9);
        uint16_t l0 = bf16_bits(a0 - bf16_back(h0));
        uint16_t l1 = bf16_bits(a1 - bf16_back(h1));
        uint16_t l8 = bf16_bits(a8 - bf16_back(h8));
        uint16_t l9 = bf16_bits(a9 - bf16_back(h9));
        v.x = ((uint32_t)h1 << 16) | h0;   // bh0
        v.y = ((uint32_t)h9 << 16) | h8;   // bh1
        v.z = ((uint32_t)l1 << 16) | l0;   // bl0
        v.w = ((uint32_t)l9 << 16) | l8;   // bl1
    }
    g_B2[idx] = v;
}

// ---------------------------------------------------------------------------
// Fused stage1+stage2: x -> o1(bf16 hi/lo in smem) -> mma.sync -> o2
// CTA: 128 threads (4 warps), 16x8 o2 output px. 3 CTAs/SM.
// smem: s_x[38][72] f32 | o1h[20][18][36] u16 | o1l same   (61.3 KB)
// B fragments: one coalesced LDG.128 per (ic, nt) from lane-linear g_B2.
// ---------------------------------------------------------------------------
#define SX_STRIDE 72
#define OFF_SX 0
#define SX_BYTES (38 * SX_STRIDE * 4)            // 10944
#define OFF_O1H SX_BYTES                          // 10944
#define O1_PLANE16 648                            // 18*36 u16 per channel
#define O1_BYTES (NC * O1_PLANE16 * 2)            // 25920
#define OFF_O1L (OFF_O1H + O1_BYTES)              // 36864
#define FK_SMEM (OFF_O1L + O1_BYTES)              // 62784

__global__ __launch_bounds__(128, 3) void fused_mma_kernel(
    const float* __restrict__ x, const float* __restrict__ w1)
{
    extern __shared__ __align__(16) char dsm[];
    float* s_x = (float*)(dsm + OFF_SX);
    uint16_t* o1h16 = (uint16_t*)(dsm + OFF_O1H);
    uint16_t* o1l16 = (uint16_t*)(dsm + OFF_O1L);
    __shared__ __align__(16) uint64_t w1p[16][10];   // [tap][oc-pair]

    const int n  = blockIdx.z;
    const int tid = threadIdx.x;
    const int ox0 = blockIdx.x * 16, oy0 = blockIdx.y * 8;
    const int rbase = 2 * oy0 - 1, cbase = 2 * ox0 - 1;   // o1-space origin
    const int xr0 = 4 * oy0 - 3,  xc0 = 4 * ox0 - 3;      // x-space origin

    // ---- w1 packed taps (160 entries, strided) -----------------------------
    for (int idx = tid; idx < 160; idx += 128) {
        int k = idx / 10, j = idx % 10;
        w1p[k][j] = pack2(w1[(2*j) * 16 + k], w1[(2*j + 1) * 16 + k]);
    }
    // ---- x tile (38 x 70, reflect) -----------------------------------------
    const float* __restrict__ xin = x + (size_t)n * H1 * H1;
    for (int i = tid; i < 38 * 70; i += 128) {
        int r = i / 70, c = i % 70;
        int gr = reflect_idx(xr0 + r, H1);
        int gc = reflect_idx(xc0 + c, H1);
        s_x[r * SX_STRIDE + c] = xin[(size_t)gr * H1 + gc];
    }
    __syncthreads();

    // ---- produce o1 (18 x 34 slots, 20 ch) as bf16 hi/lo -------------------
    for (int i = tid; i < 18 * 34; i += 128) {
        int r = i / 34, c = i % 34;
        int pr = 2 * (reflect_idx(rbase + r, H2) - rbase);
        int pc = 2 * (reflect_idx(cbase + c, H2) - cbase);
        uint64_t acc[10];
#pragma unroll
        for (int j = 0; j < 10; j++) acc[j] = 0ull;
#pragma unroll
        for (int ky = 0; ky < 4; ky++) {
            const float* xr = s_x + (pr + ky) * SX_STRIDE + pc;
            float2 A = *(const float2*)xr;
            float2 B = *(const float2*)(xr + 2);
            float v[4] = {A.x, A.y, B.x, B.y};
#pragma unroll
            for (int kx = 0; kx < 4; kx++) {
                uint64_t vb = bcast2(v[kx]);
                const uint64_t* wk = w1p[ky * 4 + kx];
#pragma unroll
                for (int j = 0; j < 10; j++) ffma2(acc[j], vb, wk[j]);
            }
        }
        int base16 = r * 36 + c;   // within a plane (u16 units)
#pragma unroll
        for (int j = 0; j < 10; j++) {
            float2 f = unpk(acc[j]);
            float v0 = fmaxf(f.x, 0.f), v1 = fmaxf(f.y, 0.f);
            uint16_t h0 = bf16_bits(v0), h1 = bf16_bits(v1);
            uint16_t l0 = bf16_bits(v0 - bf16_back(h0));
            uint16_t l1 = bf16_bits(v1 - bf16_back(h1));
            o1h16[(2*j)     * O1_PLANE16 + base16] = h0;
            o1h16[(2*j + 1) * O1_PLANE16 + base16] = h1;
            o1l16[(2*j)     * O1_PLANE16 + base16] = l0;
            o1l16[(2*j + 1) * O1_PLANE16 + base16] = l1;
        }
    }
    __syncthreads();

    // ---- consume: mma.sync, 2 m-tiles/warp x 3 n-tiles x 20 ic x 3 terms ---
    const int l = tid & 31, w = tid >> 5;
    const int g = l >> 2, q = l & 3;          // groupID, tid-in-group
    const uint32_t* o1h = (const uint32_t*)o1h16;   // [ic][18 rows][18 u32]
    const uint32_t* o1l = (const uint32_t*)o1l16;
    const int ky0 = q >> 1;
    const int kxh = q & 1;

    float acc[2][3][4];
#pragma unroll
    for (int t = 0; t < 2; t++)
#pragma unroll
        for (int nt = 0; nt < 3; nt++)
#pragma unroll
            for (int e = 0; e < 4; e++) acc[t][nt][e] = 0.f;

#pragma unroll 2
    for (int ic = 0; ic < NC; ic++) {
        // B fragments: 3 coalesced LDG.128 (lane-linear table, L1-resident)
        uint4 bfr[3];
#pragma unroll
        for (int nt = 0; nt < 3; nt++)
            bfr[nt] = __ldg(&g_B2[(ic * 3 + nt) * 32 + l]);

        const int pb = ic * 324;              // 18*18 u32 per channel
        uint32_t ah[2][4], al[2][4];
#pragma unroll
        for (int t = 0; t < 2; t++) {
            int py = 2 * w + t;
            int row_lo = pb + (2 * py + ky0) * 18;
            int row_hi = pb + (2 * py + ky0 + 2) * 18;
            ah[t][0] = o1h[row_lo + g + kxh];
            ah[t][1] = o1h[row_lo + g + 8 + kxh];
            ah[t][2] = o1h[row_hi + g + kxh];
            ah[t][3] = o1h[row_hi + g + 8 + kxh];
            al[t][0] = o1l[row_lo + g + kxh];
            al[t][1] = o1l[row_lo + g + 8 + kxh];
            al[t][2] = o1l[row_hi + g + kxh];
            al[t][3] = o1l[row_hi + g + 8 + kxh];
        }
#pragma unroll
        for (int nt = 0; nt < 3; nt++) {
#pragma unroll
            for (int t = 0; t < 2; t++) {
                mma16816(acc[t][nt], ah[t], bfr[nt].x, bfr[nt].y);   // hi*hi
                mma16816(acc[t][nt], ah[t], bfr[nt].z, bfr[nt].w);   // hi*lo
                mma16816(acc[t][nt], al[t], bfr[nt].x, bfr[nt].y);   // lo*hi
            }
        }
    }

    // ---- drain accumulators, relu, store channels-last ---------------------
#pragma unroll
    for (int t = 0; t < 2; t++) {
        int y = oy0 + 2 * w + t;
#pragma unroll
        for (int nt = 0; nt < 3; nt++) {
            int oc = nt * 8 + 2 * q;
            if (oc < NC) {
                float* p0 = g_o2 + (((size_t)n * H3 + y) * H3 + ox0 + g) * NC + oc;
                float* p1 = g_o2 + (((size_t)n * H3 + y) * H3 + ox0 + g + 8) * NC + oc;
                float2 v0 = make_float2(fmaxf(acc[t][nt][0], 0.f),
                                        fmaxf(acc[t][nt][1], 0.f));
                float2 v1 = make_float2(fmaxf(acc[t][nt][2], 0.f),
                                        fmaxf(acc[t][nt][3], 0.f));
                *(float2*)p0 = v0;
                *(float2*)p1 = v1;
            }
        }
    }
}

// ---------------------------------------------------------------------------
// Stage 3: 3x3 conv zero-pad-1 (20 -> 1) + ReLU
// tile 32x8 outputs, 128 threads; float4 gather fill, fully unrolled consume
// ---------------------------------------------------------------------------
#define S3_PLANE 362   // 10*36 + 2 pad (floats)

__global__ __launch_bounds__(128) void stage3_kernel(
    const float* __restrict__ w3, float* __restrict__ out)
{
    __shared__ __align__(16) float s_in[NC * S3_PLANE];
    __shared__ __align__(16) uint64_t s_wd[NC * 9];

    const int n  = blockIdx.z;
    const int tx = threadIdx.x, ty = threadIdx.y;   // 16 x 8
    const int tid = ty * 16 + tx;
    const int ox0 = blockIdx.x * 32, oy0 = blockIdx.y * 8;

    for (int idx = tid; idx < NC * 9; idx += 128)
        s_wd[idx] = bcast2(w3[idx]);

    // fill: 10 rows x 34 cols x 20 ch via float4 (5 per pixel)
    const float* __restrict__ ip = g_o2 + (size_t)n * H3 * H3 * NC;
    for (int i = tid; i < 340 * 5; i += 128) {
        int px = i / 5, j = i % 5;
        int r = px / 34, c = px % 34;
        int gy = oy0 - 1 + r, gx = ox0 - 1 + c;
        float4 v = make_float4(0.f, 0.f, 0.f, 0.f);
        if (gy >= 0 && gy < H3 && gx >= 0 && gx < H3)
            v = *(const float4*)(ip + ((size_t)gy * H3 + gx) * NC + 4 * j);
        float* dst = s_in + (4 * j) * S3_PLANE + r * 36 + c;
        dst[0 * S3_PLANE] = v.x;
        dst[1 * S3_PLANE] = v.y;
        dst[2 * S3_PLANE] = v.z;
        dst[3 * S3_PLANE] = v.w;
    }
    __syncthreads();

    uint64_t acc = 0ull;   // pair = outputs (ox0+2tx, ox0+2tx+1)
#pragma unroll
    for (int ic = 0; ic < NC; ic++) {
#pragma unroll
        for (int ky = 0; ky < 3; ky++) {
            const float* vr = s_in + ic * S3_PLANE + (ty + ky) * 36 + 2 * tx;
            uint64_t vA = *(const uint64_t*)(vr);
            uint64_t vB = *(const uint64_t*)(vr + 2);
            uint64_t vM = (vA >> 32) | (vB << 32);
            ffma2(acc, vA, s_wd[ic * 9 + ky * 3 + 0]);
            ffma2(acc, vM, s_wd[ic * 9 + ky * 3 + 1]);
            ffma2(acc, vB, s_wd[ic * 9 + ky * 3 + 2]);
        }
    }

    float2 f = unpk(acc);
    float2 o = make_float2(fmaxf(f.x, 0.f), fmaxf(f.y, 0.f));
    *(float2*)(out + ((size_t)n * H3 + (oy0 + ty)) * H3 + ox0 + 2 * tx) = o;
}

// ---------------------------------------------------------------------------
extern "C" void kernel_launch(void* const* d_in, const int* in_sizes, int n_in,
                              void* d_out, int out_size)
{
    const float* x  = (const float*)d_in[0];
    const float* w1 = (const float*)d_in[1];
    const float* w2 = (const float*)d_in[2];
    const float* w3 = (const float*)d_in[3];
    float* out = (float*)d_out;

    cudaFuncSetAttribute(fused_mma_kernel,
                         cudaFuncAttributeMaxDynamicSharedMemorySize, FK_SMEM);

    prep_kernel<<<8, 256>>>(w2);
    fused_mma_kernel<<<dim3(8, 16, N_IMG), dim3(128), FK_SMEM>>>(x, w1);
    stage3_kernel<<<dim3(4, 16, N_IMG), dim3(16, 8)>>>(w3, out);
}